// round 9
// baseline (speedup 1.0000x reference)
#include <cuda_runtime.h>
#include <cstdint>

// out[o,i,h,w] = sum_k weights[o,i,k] * x[k,h,w]
// OUT_CH = IN_CH = 2048, x is 3x3x3, output is (2048,2048,3,3) fp32.
//
// Persistent-CTA streaming kernel. 512 resident blocks, each owns 16
// consecutive 512-pair tiles (8192 tiles total, exact). Per tile each thread
// computes 2 pairs (18 floats), stages into one of two smem buffers, and each
// warp drains its contiguous 2304B slice with a 1D TMA bulk store. Buffers
// alternate; wait_group 1 before reuse keeps exactly one store in flight per
// warp, so compute of tile i+1 overlaps the TMA of tile i for the whole run.

__global__ void __launch_bounds__(256, 5) gf_layer_kernel(
    const float* __restrict__ x,
    const float* __restrict__ w,
    float* __restrict__ out) {
    __shared__ alignas(128) float sout[2][256 * 18];  // 2 x 18 KB buffers
    __shared__ alignas(16) float xs[28];

    const int tid = threadIdx.x;
    if (tid < 27) xs[tid] = x[tid];
    __syncthreads();

    const int wid = tid >> 5;
    const int lid = tid & 31;
    const long long tile0 = (long long)blockIdx.x * 16;

#pragma unroll 2
    for (int it = 0; it < 16; it++) {
        const int buf = it & 1;
        const long long pair0 = (tile0 + it) * 512;  // tile's first pair
        const long long p = pair0 + tid * 2;         // this thread's pair

        // 6 contiguous weights (2 pairs x 3 coeffs); 24B-aligned -> 3x
        // float2 loads. w (50MB) stays L2-resident across replays.
        const float2* __restrict__ w2 =
            reinterpret_cast<const float2*>(w + p * 3);
        const float2 wa = w2[0];
        const float2 wb = w2[1];
        const float2 wc = w2[2];
        const float wv[6] = {wa.x, wa.y, wb.x, wb.y, wc.x, wc.y};

        float o[18];
#pragma unroll
        for (int pp = 0; pp < 2; pp++) {
            const float c0 = wv[pp * 3 + 0];
            const float c1 = wv[pp * 3 + 1];
            const float c2 = wv[pp * 3 + 2];
#pragma unroll
            for (int j = 0; j < 9; j++) {
                o[pp * 9 + j] =
                    fmaf(c0, xs[j], fmaf(c1, xs[9 + j], c2 * xs[18 + j]));
            }
        }

        // Before overwriting this buffer, the TMA issued from it 2 iters ago
        // must have retired: allow at most 1 pending group (the other buf).
        if (lid == 0) {
            asm volatile("cp.async.bulk.wait_group 1;" ::: "memory");
        }
        __syncwarp();

        // Stage to smem as float2: thread stride = 18 floats = 72B. STS.64
        // phase = 16 lanes; banks (18*l) mod 32 are 16 distinct even values
        // -> conflict-free.
        float2* __restrict__ s2 =
            reinterpret_cast<float2*>(&sout[buf][0] + tid * 18);
#pragma unroll
        for (int i = 0; i < 9; i++) {
            s2[i] = make_float2(o[2 * i], o[2 * i + 1]);
        }

        __syncwarp();

        // Per-warp TMA drain: warp wid owns 2304 contiguous bytes of the tile.
        if (lid == 0) {
            const float* ssrc = &sout[buf][0] + wid * (32 * 18);
            uint32_t saddr;
            asm("{ .reg .u64 q; cvta.to.shared.u64 q, %1; cvt.u32.u64 %0, q; }"
                : "=r"(saddr) : "l"(ssrc));
            float* gdst = out + pair0 * 9 + wid * (32 * 18);
            asm volatile("fence.proxy.async.shared::cta;" ::: "memory");
            asm volatile(
                "cp.async.bulk.global.shared::cta.bulk_group [%0], [%1], %2;"
                :: "l"(gdst), "r"(saddr), "r"(32 * 18 * 4) : "memory");
            asm volatile("cp.async.bulk.commit_group;" ::: "memory");
        }
    }

    // Drain all remaining in-flight bulk stores before smem teardown.
    if (lid == 0) {
        asm volatile("cp.async.bulk.wait_group 0;" ::: "memory");
    }
}

extern "C" void kernel_launch(void* const* d_in, const int* in_sizes, int n_in,
                              void* d_out, int out_size) {
    // Inputs: x (27 elems), weights (2048*2048*3). Identify x by element count.
    const float* x;
    const float* w;
    long long w_elems;
    if (in_sizes[0] == 27) {
        x = (const float*)d_in[0];
        w = (const float*)d_in[1];
        w_elems = in_sizes[1];
    } else {
        x = (const float*)d_in[1];
        w = (const float*)d_in[0];
        w_elems = in_sizes[0];
    }

    float* out = (float*)d_out;

    // total_pairs = 4,194,304 -> 8192 tiles of 512 pairs -> 512 blocks x 16.
    (void)w_elems;
    gf_layer_kernel<<<512, 256>>>(x, w, out);
}

// round 10
// speedup vs baseline: 1.1728x; 1.1728x over previous
#include <cuda_runtime.h>
#include <cstdint>

// out[o,i,h,w] = sum_k weights[o,i,k] * x[k,h,w]
// OUT_CH = IN_CH = 2048, x is 3x3x3, output is (2048,2048,3,3) fp32.
//
// Streaming kernel, 128-thread blocks (fine granularity so per-block TMA tail
// waits idle only 4 warps and ~12 co-resident blocks/SM backfill). Each
// thread computes 2 (o,i) pairs (18 floats), stages them in smem, and each
// warp drains its contiguous 2304B slice with its own 1D TMA bulk store.

__global__ void __launch_bounds__(128, 12) gf_layer_kernel(
    const float* __restrict__ x,
    const float* __restrict__ w,
    float* __restrict__ out) {
    __shared__ alignas(128) float sout[128 * 18];  // 9 KB staging tile
    __shared__ alignas(16) float xs[28];

    const int tid = threadIdx.x;
    if (tid < 27) xs[tid] = x[tid];
    __syncthreads();

    // First (o,i) pair handled by this thread (2 pairs per thread).
    const long long p = ((long long)blockIdx.x * 128 + tid) * 2;

    // 6 contiguous weights (2 pairs x 3 coeffs); byte offset p*12 is
    // 24B-aligned -> 3x float2 loads. w (50MB) stays L2-resident.
    const float2* __restrict__ w2 = reinterpret_cast<const float2*>(w + p * 3);
    const float2 wa = w2[0];
    const float2 wb = w2[1];
    const float2 wc = w2[2];
    const float wv[6] = {wa.x, wa.y, wb.x, wb.y, wc.x, wc.y};

    float o[18];
#pragma unroll
    for (int pp = 0; pp < 2; pp++) {
        const float c0 = wv[pp * 3 + 0];
        const float c1 = wv[pp * 3 + 1];
        const float c2 = wv[pp * 3 + 2];
#pragma unroll
        for (int j = 0; j < 9; j++) {
            o[pp * 9 + j] = fmaf(c0, xs[j], fmaf(c1, xs[9 + j], c2 * xs[18 + j]));
        }
    }

    // Stage to smem as float2: thread stride = 18 floats = 72B. STS.64 phase
    // = 16 lanes; banks (18*l) mod 32 are 16 distinct even values ->
    // conflict-free.
    float2* __restrict__ s2 = reinterpret_cast<float2*>(sout + tid * 18);
#pragma unroll
    for (int i = 0; i < 9; i++) {
        s2[i] = make_float2(o[2 * i], o[2 * i + 1]);
    }

    // Per-warp TMA drain: warp wid owns sout[wid*576 .. +576) = 2304 bytes,
    // contiguous in both smem and gmem.
    const int wid = tid >> 5;
    const int lid = tid & 31;
    __syncwarp();

    if (lid == 0) {
        const float* ssrc = sout + wid * (32 * 18);
        uint32_t saddr;
        asm("{ .reg .u64 t; cvta.to.shared.u64 t, %1; cvt.u32.u64 %0, t; }"
            : "=r"(saddr) : "l"(ssrc));
        float* gdst = out + (long long)blockIdx.x * (128 * 18) + wid * (32 * 18);
        asm volatile("fence.proxy.async.shared::cta;" ::: "memory");
        asm volatile(
            "cp.async.bulk.global.shared::cta.bulk_group [%0], [%1], %2;"
            :: "l"(gdst), "r"(saddr), "r"(32 * 18 * 4) : "memory");
        asm volatile("cp.async.bulk.commit_group;" ::: "memory");
        // Wait before this warp's smem slice may be torn down (block exit).
        asm volatile("cp.async.bulk.wait_group 0;" ::: "memory");
    }
}

extern "C" void kernel_launch(void* const* d_in, const int* in_sizes, int n_in,
                              void* d_out, int out_size) {
    // Inputs: x (27 elems), weights (2048*2048*3). Identify x by element count.
    const float* x;
    const float* w;
    long long w_elems;
    if (in_sizes[0] == 27) {
        x = (const float*)d_in[0];
        w = (const float*)d_in[1];
        w_elems = in_sizes[1];
    } else {
        x = (const float*)d_in[1];
        w = (const float*)d_in[0];
        w_elems = in_sizes[0];
    }

    float* out = (float*)d_out;

    const long long total_pairs = w_elems / 3;   // (o,i) pairs = 4,194,304
    const long long pairs_per_block = 128 * 2;   // 256
    const int blocks = (int)(total_pairs / pairs_per_block);  // 16384, exact

    gf_layer_kernel<<<blocks, 128>>>(x, w, out);
}